// round 1
// baseline (speedup 1.0000x reference)
#include <cuda_runtime.h>
#include <cuda_bf16.h>
#include <cstdint>

// Flash attention, tf32 mma.sync, fp32 accumulate.
// B=2, L=4096, H=8, D=64. Br=Bc=64, 4 warps (128 thr) per CTA.
// Layout [B, L, H, D]: row stride H*D = 512 floats, D contiguous.

#define LSEQ 4096
#define NB   2
#define NH   8
#define DH   64
#define BQ   64
#define BK   64
#define GSTRIDE (NH*DH)   // 512 floats between consecutive seq positions

#define KS_STRIDE 68
#define VS_STRIDE 72
#define PS_STRIDE 68

__device__ __forceinline__ unsigned f2tf(float x) {
    unsigned u;
    asm("cvt.rna.tf32.f32 %0, %1;" : "=r"(u) : "f"(x));
    return u;
}

__device__ __forceinline__ float ex2f(float x) {
    float y;
    asm("ex2.approx.ftz.f32 %0, %1;" : "=f"(y) : "f"(x));
    return y;
}

__device__ __forceinline__ void mma_tf32(float* d, const unsigned* a, unsigned b0, unsigned b1) {
    asm volatile(
        "mma.sync.aligned.m16n8k8.row.col.f32.tf32.tf32.f32 "
        "{%0,%1,%2,%3},{%4,%5,%6,%7},{%8,%9},{%0,%1,%2,%3};\n"
        : "+f"(d[0]), "+f"(d[1]), "+f"(d[2]), "+f"(d[3])
        : "r"(a[0]), "r"(a[1]), "r"(a[2]), "r"(a[3]), "r"(b0), "r"(b1));
}

extern "C" __global__ void __launch_bounds__(128)
attn_tf32_kernel(const float* __restrict__ Q,
                 const float* __restrict__ K,
                 const float* __restrict__ V,
                 float* __restrict__ O) {
    extern __shared__ float sm[];
    float* ks = sm;                        // 64 x 68
    float* vs = ks + BK * KS_STRIDE;       // 64 x 72
    float* ps = vs + BK * VS_STRIDE;       // 64 x 68

    const int tid  = threadIdx.x;
    const int lane = tid & 31;
    const int warp = tid >> 5;
    const int gr   = lane >> 2;   // group row within 8
    const int gc   = lane & 3;    // thread-in-group (column group)

    const int qt = blockIdx.x;    // q tile
    const int h  = blockIdx.y;
    const int b  = blockIdx.z;
    const int q0 = qt * BQ;

    const float* Qg = Q + ((size_t)((b * LSEQ + q0) * NH + h)) * DH;

    // ---- stage Q tile into ks, build tf32 A-fragments (register resident) ----
    #pragma unroll
    for (int i = 0; i < 8; i++) {
        int lin = i * 128 + tid;
        int r = lin >> 4, c4 = lin & 15;
        float4 v = *(const float4*)(Qg + (size_t)r * GSTRIDE + c4 * 4);
        *(float4*)(ks + r * KS_STRIDE + c4 * 4) = v;
    }
    __syncthreads();

    const int r0 = warp * 16 + gr;    // this thread's first q-row (local)

    unsigned qa[8][4];
    #pragma unroll
    for (int k = 0; k < 8; k++) {
        int c = k * 8 + gc;
        qa[k][0] = f2tf(ks[r0 * KS_STRIDE + c]);
        qa[k][1] = f2tf(ks[(r0 + 8) * KS_STRIDE + c]);
        qa[k][2] = f2tf(ks[r0 * KS_STRIDE + c + 4]);
        qa[k][3] = f2tf(ks[(r0 + 8) * KS_STRIDE + c + 4]);
    }
    __syncthreads();

    float o[8][4];
    #pragma unroll
    for (int n = 0; n < 8; n++) { o[n][0] = o[n][1] = o[n][2] = o[n][3] = 0.f; }
    float m0 = -1e30f, m1 = -1e30f, l0 = 0.f, l1 = 0.f;
    const float sc2 = 0.125f * 1.4426950408889634f;   // scale * log2(e)

    const float* Kg0 = K + ((size_t)((b * LSEQ) * NH + h)) * DH;
    const float* Vg0 = V + ((size_t)((b * LSEQ) * NH + h)) * DH;

    for (int j = 0; j < LSEQ / BK; j++) {
        const float* Kg = Kg0 + (size_t)j * BK * GSTRIDE;
        const float* Vg = Vg0 + (size_t)j * BK * GSTRIDE;

        #pragma unroll
        for (int i = 0; i < 8; i++) {
            int lin = i * 128 + tid;
            int r = lin >> 4, c4 = lin & 15;
            *(float4*)(ks + r * KS_STRIDE + c4 * 4) =
                *(const float4*)(Kg + (size_t)r * GSTRIDE + c4 * 4);
            *(float4*)(vs + r * VS_STRIDE + c4 * 4) =
                *(const float4*)(Vg + (size_t)r * GSTRIDE + c4 * 4);
        }
        __syncthreads();

        // ---- S = Q K^T (64x64 per CTA; 16x64 per warp) ----
        float s[8][4];
        #pragma unroll
        for (int n = 0; n < 8; n++) { s[n][0] = s[n][1] = s[n][2] = s[n][3] = 0.f; }

        #pragma unroll
        for (int k = 0; k < 8; k++) {
            #pragma unroll
            for (int n = 0; n < 8; n++) {
                int idx = (n * 8 + gr) * KS_STRIDE + k * 8 + gc;
                unsigned b0 = f2tf(ks[idx]);
                unsigned b1 = f2tf(ks[idx + 4]);
                mma_tf32(s[n], qa[k], b0, b1);
            }
        }

        // ---- online softmax (rows r0 and r0+8) ----
        float mx0 = -1e30f, mx1 = -1e30f;
        #pragma unroll
        for (int n = 0; n < 8; n++) {
            mx0 = fmaxf(mx0, fmaxf(s[n][0], s[n][1]));
            mx1 = fmaxf(mx1, fmaxf(s[n][2], s[n][3]));
        }
        mx0 = fmaxf(mx0, __shfl_xor_sync(0xffffffffu, mx0, 1));
        mx0 = fmaxf(mx0, __shfl_xor_sync(0xffffffffu, mx0, 2));
        mx1 = fmaxf(mx1, __shfl_xor_sync(0xffffffffu, mx1, 1));
        mx1 = fmaxf(mx1, __shfl_xor_sync(0xffffffffu, mx1, 2));

        float m0n = fmaxf(m0, mx0);
        float m1n = fmaxf(m1, mx1);
        float al0 = ex2f((m0 - m0n) * sc2);
        float al1 = ex2f((m1 - m1n) * sc2);
        float mb0 = m0n * sc2;
        float mb1 = m1n * sc2;

        float rs0 = 0.f, rs1 = 0.f;
        #pragma unroll
        for (int n = 0; n < 8; n++) {
            s[n][0] = ex2f(fmaf(s[n][0], sc2, -mb0));
            s[n][1] = ex2f(fmaf(s[n][1], sc2, -mb0));
            s[n][2] = ex2f(fmaf(s[n][2], sc2, -mb1));
            s[n][3] = ex2f(fmaf(s[n][3], sc2, -mb1));
            rs0 += s[n][0] + s[n][1];
            rs1 += s[n][2] + s[n][3];
        }
        rs0 += __shfl_xor_sync(0xffffffffu, rs0, 1);
        rs0 += __shfl_xor_sync(0xffffffffu, rs0, 2);
        rs1 += __shfl_xor_sync(0xffffffffu, rs1, 1);
        rs1 += __shfl_xor_sync(0xffffffffu, rs1, 2);

        l0 = l0 * al0 + rs0;
        l1 = l1 * al1 + rs1;
        #pragma unroll
        for (int n = 0; n < 8; n++) {
            o[n][0] *= al0; o[n][1] *= al0;
            o[n][2] *= al1; o[n][3] *= al1;
        }
        m0 = m0n; m1 = m1n;

        // ---- store P (warp-private rows) in tf32-rounded form ----
        #pragma unroll
        for (int n = 0; n < 8; n++) {
            int base = r0 * PS_STRIDE + n * 8 + gc * 2;
            *(float2*)(ps + base) =
                make_float2(__uint_as_float(f2tf(s[n][0])), __uint_as_float(f2tf(s[n][1])));
            *(float2*)(ps + base + 8 * PS_STRIDE) =
                make_float2(__uint_as_float(f2tf(s[n][2])), __uint_as_float(f2tf(s[n][3])));
        }
        __syncwarp();

        // ---- O += P V ----
        #pragma unroll
        for (int k = 0; k < 8; k++) {
            int pr = r0 * PS_STRIDE + k * 8 + gc;
            unsigned pa[4];
            pa[0] = __float_as_uint(ps[pr]);
            pa[1] = __float_as_uint(ps[pr + 8 * PS_STRIDE]);
            pa[2] = __float_as_uint(ps[pr + 4]);
            pa[3] = __float_as_uint(ps[pr + 8 * PS_STRIDE + 4]);
            #pragma unroll
            for (int n = 0; n < 8; n++) {
                int vr = (k * 8 + gc) * VS_STRIDE + n * 8 + gr;
                unsigned b0 = f2tf(vs[vr]);
                unsigned b1 = f2tf(vs[vr + 4 * VS_STRIDE]);
                mma_tf32(o[n], pa, b0, b1);
            }
        }
        __syncthreads();
    }

    // ---- finalize and store ----
    float inv0 = 1.f / l0;
    float inv1 = 1.f / l1;
    float* Og  = O + ((size_t)((b * LSEQ + q0 + r0) * NH + h)) * DH;
    float* Og8 = O + ((size_t)((b * LSEQ + q0 + r0 + 8) * NH + h)) * DH;
    #pragma unroll
    for (int n = 0; n < 8; n++) {
        int c = n * 8 + gc * 2;
        *(float2*)(Og + c)  = make_float2(o[n][0] * inv0, o[n][1] * inv0);
        *(float2*)(Og8 + c) = make_float2(o[n][2] * inv1, o[n][3] * inv1);
    }
}

extern "C" void kernel_launch(void* const* d_in, const int* in_sizes, int n_in,
                              void* d_out, int out_size) {
    const float* Q = (const float*)d_in[0];
    const float* K = (const float*)d_in[1];
    const float* V = (const float*)d_in[2];
    float* O = (float*)d_out;

    const int smem_bytes = (BK * KS_STRIDE + BK * VS_STRIDE + BQ * PS_STRIDE) * 4;  // 53248
    cudaFuncSetAttribute(attn_tf32_kernel,
                         cudaFuncAttributeMaxDynamicSharedMemorySize, smem_bytes);

    dim3 grid(LSEQ / BQ, NH, NB);
    attn_tf32_kernel<<<grid, 128, smem_bytes>>>(Q, K, V, O);
}